// round 15
// baseline (speedup 1.0000x reference)
#include <cuda_runtime.h>

#define B_   64
#define T_   13
#define N_   325
#define H_   64
#define C_   4
#define S_   4
#define P_   12
#define NB_  1300
#define OFF_ 975
#define NH_  (N_*H_)        // 20800
#define BNH_ (B_*NH_)       // 1331200
#define ROW_ (B_*H_)        // 4096 floats per node row (node-major)

typedef unsigned long long u64;

// ---------------- scratch (device globals; no runtime alloc allowed) --------
__device__ float  g_gf  [BNH_];
__device__ float  g_res [BNH_];
__device__ float  g_h3T [BNH_];          // node-major [n][b*64+h]
__device__ float  g_cr  [BNH_];
__device__ float  g_H0T [2][C_][BNH_];   // node-major layer-0 outputs
__device__ float  g_C1  [2][C_][BNH_];   // batch-major (for k_gate)
__device__ float  g_Wsum[2][C_][2][H_*H_];
__device__ int    g_cols[2][N_][N_];
__device__ float  g_vals[2][N_][N_];
__device__ int    g_cnt [2][N_];
__device__ double g_sumsA[4][2];         // per-checkpoint (sum, sumsq)

// ---------------- f32x2 packed helpers (used by k_gate) ---------------------
__device__ __forceinline__ u64 pack2(float x, float y) {
    u64 r;
    asm("mov.b64 %0, {%1, %2};" : "=l"(r) : "f"(x), "f"(y));
    return r;
}
__device__ __forceinline__ float2 unpack2(u64 v) {
    float2 r;
    asm("mov.b64 {%0, %1}, %2;" : "=f"(r.x), "=f"(r.y) : "l"(v));
    return r;
}
__device__ __forceinline__ void fma2(u64& d, u64 a, u64 b) {
    asm("fma.rn.f32x2 %0, %1, %2, %0;" : "+l"(d) : "l"(a), "l"(b));
}
__device__ __forceinline__ void gemm_step(u64 accA[4], u64 accB[4],
                                          u64 a0, u64 a1, u64 a2, u64 a3,
                                          float4 w) {
    u64 wxy = pack2(w.x, w.y);
    u64 wzw = pack2(w.z, w.w);
    fma2(accA[0], a0, wxy); fma2(accB[0], a0, wzw);
    fma2(accA[1], a1, wxy); fma2(accB[1], a1, wzw);
    fma2(accA[2], a2, wxy); fma2(accB[2], a2, wzw);
    fma2(accA[3], a3, wxy); fma2(accB[3], a3, wzw);
}

// ---------------- scalar 4x4 helpers -----------------------------------------
__device__ __forceinline__ void fma16(float4 acc[4], float a0, float a1, float a2,
                                      float a3, float4 w) {
    acc[0].x = fmaf(a0, w.x, acc[0].x); acc[0].y = fmaf(a0, w.y, acc[0].y);
    acc[0].z = fmaf(a0, w.z, acc[0].z); acc[0].w = fmaf(a0, w.w, acc[0].w);
    acc[1].x = fmaf(a1, w.x, acc[1].x); acc[1].y = fmaf(a1, w.y, acc[1].y);
    acc[1].z = fmaf(a1, w.z, acc[1].z); acc[1].w = fmaf(a1, w.w, acc[1].w);
    acc[2].x = fmaf(a2, w.x, acc[2].x); acc[2].y = fmaf(a2, w.y, acc[2].y);
    acc[2].z = fmaf(a2, w.z, acc[2].z); acc[2].w = fmaf(a2, w.w, acc[2].w);
    acc[3].x = fmaf(a3, w.x, acc[3].x); acc[3].y = fmaf(a3, w.y, acc[3].y);
    acc[3].z = fmaf(a3, w.z, acc[3].z); acc[3].w = fmaf(a3, w.w, acc[3].w);
}
__device__ __forceinline__ float4 relu4(float4 v) {
    v.x = v.x > 0.f ? v.x : 0.f; v.y = v.y > 0.f ? v.y : 0.f;
    v.z = v.z > 0.f ? v.z : 0.f; v.w = v.w > 0.f ? v.w : 0.f;
    return v;
}
__device__ __forceinline__ void fma4v(float4& a, float w, float4 v) {
    a.x = fmaf(w, v.x, a.x); a.y = fmaf(w, v.y, a.y);
    a.z = fmaf(w, v.z, a.z); a.w = fmaf(w, v.w, a.w);
}

// ---------------- prep: Wsum[mat][c][l] = W[c,l,0] + W[c,l,1]; zero sums ----
__global__ void k_wsum(const float* __restrict__ aw, const float* __restrict__ pw) {
    int idx = blockIdx.x * blockDim.x + threadIdx.x;
    if (idx < 8) ((double*)g_sumsA)[idx] = 0.0;
    if (idx >= 2 * C_ * 2 * H_ * H_) return;
    int mat = idx >> 15;
    int r   = idx & 32767;
    int c   = r >> 13;
    int l   = (r >> 12) & 1;
    int e   = r & 4095;
    const float* src = mat ? pw : aw;
    int base = ((c * 2 + l) * 2) * 4096;
    ((float*)g_Wsum)[idx] = src[base + e] + src[base + 4096 + e];
}

// ---------------- prep: compact nonzeros of the last diagonal block ---------
__global__ void k_compact(const float* __restrict__ adjf, const float* __restrict__ peaf) {
    int rowid = blockIdx.x;
    int mat = rowid / N_;
    int n   = rowid % N_;
    const float* A = mat ? peaf : adjf;
    int lane = threadIdx.x;
    int cnt = 0;
    for (int base = 0; base < N_; base += 32) {
        int m = base + lane;
        float w = (m < N_) ? A[(long)(OFF_ + n) * NB_ + OFF_ + m] : 0.f;
        unsigned mask = __ballot_sync(0xffffffffu, w != 0.f);
        if (w != 0.f) {
            int pos = cnt + __popc(mask & ((1u << lane) - 1u));
            g_cols[mat][n][pos] = m;
            g_vals[mat][n][pos] = w;
        }
        cnt += __popc(mask);
    }
    if (lane == 0) g_cnt[mat][n] = cnt;
}

// ---------------- per-checkpoint: gf / residual / h3T (x + norm inline) -----
__global__ void k_A(const float* __restrict__ inp, const float* __restrict__ w_in,
                    const float* __restrict__ b_in, const float* __restrict__ res_w,
                    const float* __restrict__ res_b, const float* __restrict__ gcw,
                    const float* __restrict__ gcb, int ck, int left) {
    __shared__ float s_mu, s_r;
    if (threadIdx.x == 0) {
        if (ck > 0) {
            double mu  = g_sumsA[ck - 1][0] / (double)BNH_;
            double var = g_sumsA[ck - 1][1] / (double)BNH_ - mu * mu;
            s_mu = (float)mu;
            s_r  = (float)rsqrt(var + 1e-5);
        } else { s_mu = 0.f; s_r = 0.f; }
    }
    __syncthreads();
    int idx = blockIdx.x * blockDim.x + threadIdx.x;
    if (idx >= BNH_) return;
    int h = idx & 63;
    int n = (idx >> 6) % N_;
    int b = idx / NH_;
    float w0 = w_in[h], w1 = w_in[64 + h], bi = b_in[h];
    float gf = 0.f, rs = 0.f, v = 0.f;
#pragma unroll
    for (int s = 0; s < 4; ++s) {
        if (ck > 0 && s == 0) {
            v = (g_cr[idx] - s_mu) * s_r;
        } else {
            int t = (ck == 0) ? s : (left + s - 1);
            const float2 ip = *(const float2*)(inp + (((long)b * T_ + t) * N_ + n) * 2);
            v = ip.x * w0 + ip.y * w1 + bi;
        }
        gf += gcw[s] * v;
        rs += res_w[s] * v;
    }
    g_gf[idx]  = gf + gcb[0];
    g_res[idx] = rs + res_b[0];
    g_h3T[(long)n * ROW_ + b * 64 + h] = v;     // node-major
}

// -------- GCN layer 0: coalesced streaming SpMM + 4x4-tiled GEMMs -----------
// grid (N_, 2 batch-groups, 2 mats); block 128
__global__ void __launch_bounds__(128) k_layer0(const float* __restrict__ gbA,
                                                const float* __restrict__ gbP) {
    __shared__ int   scols[336];
    __shared__ float svals[336];
    __shared__ float sA[32][64];       // [b][h] slice for 32 batches
    int n   = blockIdx.x;
    int bg  = blockIdx.y;
    int mat = blockIdx.z;
    int t   = threadIdx.x;
    int cnt = g_cnt[mat][n];
    for (int i = t; i < cnt; i += 128) {
        scols[i] = g_cols[mat][n][i];
        svals[i] = g_vals[mat][n][i];
    }
    __syncthreads();

    {   // streaming SpMM: per nonzero, read contiguous 8KB slice of node row
        const float4* base = (const float4*)g_h3T + bg * 512 + t;
        float4 a0 = make_float4(0.f,0.f,0.f,0.f), a1 = a0, a2 = a0, a3 = a0;
        for (int i = 0; i < cnt; ++i) {
            const float4* src = base + (long)scols[i] * (ROW_ / 4);
            float w = svals[i];
            float4 v0 = src[0];
            float4 v1 = src[128];
            float4 v2 = src[256];
            float4 v3 = src[384];
            fma4v(a0, w, v0); fma4v(a1, w, v1);
            fma4v(a2, w, v2); fma4v(a3, w, v3);
        }
        float4* s4 = (float4*)sA;
        s4[t] = a0; s4[t + 128] = a1; s4[t + 256] = a2; s4[t + 384] = a3;
    }
    __syncthreads();

    int tx = t & 15, ty = t >> 4;      // ty 0..7 -> 4 batches each
    const float* gb = mat ? gbP : gbA;
#pragma unroll
    for (int c = 0; c < C_; ++c) {
        const float4* W4 = (const float4*)g_Wsum[mat][c][0] + tx;
        float4 bias = ((const float4*)(gb + (c * 2) * 64))[tx];
        float4 acc[4] = {bias, bias, bias, bias};
        const float* A0 = sA[ty * 4 + 0];
        const float* A1 = sA[ty * 4 + 1];
        const float* A2 = sA[ty * 4 + 2];
        const float* A3 = sA[ty * 4 + 3];
#pragma unroll 4
        for (int k = 0; k < 64; ++k)
            fma16(acc, A0[k], A1[k], A2[k], A3[k], __ldg(&W4[k * 16]));
        float* dst = g_H0T[mat][c] + (long)n * ROW_ + bg * 2048 + tx * 4;
#pragma unroll
        for (int j = 0; j < 4; ++j)
            *(float4*)(dst + (ty * 4 + j) * 64) = relu4(acc[j]);
    }
}

// -------- GCN layer 1: per-channel streaming SpMM + GEMM (C1 batch-major) ---
// grid (N_, 2, 2); block 128
__global__ void __launch_bounds__(128) k_layer1(const float* __restrict__ gbA,
                                                const float* __restrict__ gbP) {
    __shared__ int   scols[336];
    __shared__ float svals[336];
    __shared__ float sA[32][64];
    int n   = blockIdx.x;
    int bg  = blockIdx.y;
    int mat = blockIdx.z;
    int t   = threadIdx.x;
    int cnt = g_cnt[mat][n];
    for (int i = t; i < cnt; i += 128) {
        scols[i] = g_cols[mat][n][i];
        svals[i] = g_vals[mat][n][i];
    }
    __syncthreads();

    int tx = t & 15, ty = t >> 4;
    const float* gb = mat ? gbP : gbA;
#pragma unroll
    for (int c = 0; c < C_; ++c) {
        if (c) __syncthreads();        // prev GEMM finished reading sA
        {   // streaming SpMM from H0T[mat][c]
            const float4* base = (const float4*)g_H0T[mat][c] + bg * 512 + t;
            float4 a0 = make_float4(0.f,0.f,0.f,0.f), a1 = a0, a2 = a0, a3 = a0;
            for (int i = 0; i < cnt; ++i) {
                const float4* src = base + (long)scols[i] * (ROW_ / 4);
                float w = svals[i];
                float4 v0 = src[0];
                float4 v1 = src[128];
                float4 v2 = src[256];
                float4 v3 = src[384];
                fma4v(a0, w, v0); fma4v(a1, w, v1);
                fma4v(a2, w, v2); fma4v(a3, w, v3);
            }
            float4* s4 = (float4*)sA;
            s4[t] = a0; s4[t + 128] = a1; s4[t + 256] = a2; s4[t + 384] = a3;
        }
        __syncthreads();
        {   // GEMM with Wsum[mat][c][1] -> g_C1 batch-major
            const float4* W4 = (const float4*)g_Wsum[mat][c][1] + tx;
            float4 bias = ((const float4*)(gb + (c * 2 + 1) * 64))[tx];
            float4 acc[4] = {bias, bias, bias, bias};
            const float* A0 = sA[ty * 4 + 0];
            const float* A1 = sA[ty * 4 + 1];
            const float* A2 = sA[ty * 4 + 2];
            const float* A3 = sA[ty * 4 + 3];
#pragma unroll 4
            for (int k = 0; k < 64; ++k)
                fma16(acc, A0[k], A1[k], A2[k], A3[k], __ldg(&W4[k * 16]));
            float* dst = g_C1[mat][c] + n * 64 + tx * 4;
#pragma unroll
            for (int j = 0; j < 4; ++j)
                *(float4*)(dst + (long)(bg * 32 + ty * 4 + j) * NH_) = relu4(acc[j]);
        }
    }
}

// ------- gate -> combine -> reduce -> +residual, fused LN partial sums ------
__global__ void __launch_bounds__(128) k_gate(
        const float* __restrict__ g1w, const float* __restrict__ g1b,
        const float* __restrict__ g2w, const float* __restrict__ g2b,
        const float* __restrict__ rw,  const float* __restrict__ rb, int ck) {
    __shared__ float2 sBuf[32][64];
    __shared__ float2 sG1[32][64];
    __shared__ double reds[4], redq[4];
    int t = threadIdx.x;
    long row0 = (long)blockIdx.x * 32;

    {   // load gf tile (duplicated pairs)
        const float* src = g_gf + row0 * 64;
#pragma unroll
        for (int i = 0; i < 16; ++i) {
            int idx = t + 128 * i;
            float v = src[idx];
            ((float2*)sBuf)[idx] = make_float2(v, v);
        }
    }
    __syncthreads();

    int tx = t & 15, ty = t >> 4;
    {   // stage 1: relu(gf @ g1w + g1b) -> sG1 (duplicated)
        const float4* W4 = (const float4*)g1w + tx;
        float4 b1 = ((const float4*)g1b)[tx];
        u64 bA = pack2(b1.x, b1.y), bB = pack2(b1.z, b1.w);
        u64 accA[4] = {bA, bA, bA, bA};
        u64 accB[4] = {bB, bB, bB, bB};
        const float2* A0 = sBuf[ty * 4 + 0];
        const float2* A1 = sBuf[ty * 4 + 1];
        const float2* A2 = sBuf[ty * 4 + 2];
        const float2* A3 = sBuf[ty * 4 + 3];
#pragma unroll 4
        for (int k = 0; k < 64; ++k) {
            gemm_step(accA, accB,
                      *(const u64*)&A0[k], *(const u64*)&A1[k],
                      *(const u64*)&A2[k], *(const u64*)&A3[k],
                      __ldg(&W4[k * 16]));
        }
#pragma unroll
        for (int j = 0; j < 4; ++j) {
            float2 lo = unpack2(accA[j]);
            float2 hi = unpack2(accB[j]);
            float r0 = lo.x > 0.f ? lo.x : 0.f;
            float r1 = lo.y > 0.f ? lo.y : 0.f;
            float r2 = hi.x > 0.f ? hi.x : 0.f;
            float r3 = hi.y > 0.f ? hi.y : 0.f;
            sG1[ty * 4 + j][tx * 4 + 0] = make_float2(r0, r0);
            sG1[ty * 4 + j][tx * 4 + 1] = make_float2(r1, r1);
            sG1[ty * 4 + j][tx * 4 + 2] = make_float2(r2, r2);
            sG1[ty * 4 + j][tx * 4 + 3] = make_float2(r3, r3);
        }
    }
    __syncthreads();

    float4 rbv = ((const float4*)rb)[tx];
    u64 r3A = pack2(rbv.x, rbv.y), r3B = pack2(rbv.z, rbv.w);
    u64 acc3A[4] = {r3A, r3A, r3A, r3A};
    u64 acc3B[4] = {r3B, r3B, r3B, r3B};
#pragma unroll
    for (int q = 0; q < 4; ++q) {
        float4 b2 = ((const float4*)(g2b + q * 64))[tx];
        u64 bA = pack2(b2.x, b2.y), bB = pack2(b2.z, b2.w);
        u64 acc2A[4] = {bA, bA, bA, bA};
        u64 acc2B[4] = {bB, bB, bB, bB};
        {
            const float4* W4 = (const float4*)(g2w + q * 64) + tx;
            const float2* A0 = sG1[ty * 4 + 0];
            const float2* A1 = sG1[ty * 4 + 1];
            const float2* A2 = sG1[ty * 4 + 2];
            const float2* A3 = sG1[ty * 4 + 3];
#pragma unroll 4
            for (int k = 0; k < 64; ++k) {
                gemm_step(acc2A, acc2B,
                          *(const u64*)&A0[k], *(const u64*)&A1[k],
                          *(const u64*)&A2[k], *(const u64*)&A3[k],
                          __ldg(&W4[k * 64]));
            }
        }
        __syncthreads();
#pragma unroll
        for (int j = 0; j < 4; ++j) {
            long rr = (row0 + ty * 4 + j) * 64 + tx * 4;
            float4 ca = *(const float4*)&g_C1[0][q][rr];
            float4 cp = *(const float4*)&g_C1[1][q][rr];
            float2 lo = unpack2(acc2A[j]);
            float2 hi = unpack2(acc2B[j]);
            float g0 = 1.f / (1.f + expf(-lo.x));
            float g1 = 1.f / (1.f + expf(-lo.y));
            float g2 = 1.f / (1.f + expf(-hi.x));
            float g3 = 1.f / (1.f + expf(-hi.y));
            float o0 = g0 * ca.x + (1.f - g0) * cp.x;
            float o1 = g1 * ca.y + (1.f - g1) * cp.y;
            float o2 = g2 * ca.z + (1.f - g2) * cp.z;
            float o3 = g3 * ca.w + (1.f - g3) * cp.w;
            sBuf[ty * 4 + j][tx * 4 + 0] = make_float2(o0, o0);
            sBuf[ty * 4 + j][tx * 4 + 1] = make_float2(o1, o1);
            sBuf[ty * 4 + j][tx * 4 + 2] = make_float2(o2, o2);
            sBuf[ty * 4 + j][tx * 4 + 3] = make_float2(o3, o3);
        }
        __syncthreads();
        {
            const float4* W4 = (const float4*)(rw + (q * 64) * 64) + tx;
            const float2* A0 = sBuf[ty * 4 + 0];
            const float2* A1 = sBuf[ty * 4 + 1];
            const float2* A2 = sBuf[ty * 4 + 2];
            const float2* A3 = sBuf[ty * 4 + 3];
#pragma unroll 4
            for (int k = 0; k < 64; ++k) {
                gemm_step(acc3A, acc3B,
                          *(const u64*)&A0[k], *(const u64*)&A1[k],
                          *(const u64*)&A2[k], *(const u64*)&A3[k],
                          __ldg(&W4[k * 16]));
            }
        }
    }

    double ls = 0.0, lq = 0.0;
#pragma unroll
    for (int j = 0; j < 4; ++j) {
        long rr = (row0 + ty * 4 + j) * 64 + tx * 4;
        float4 rv = *(const float4*)&g_res[rr];
        float2 lo = unpack2(acc3A[j]);
        float2 hi = unpack2(acc3B[j]);
        float4 v;
        v.x = lo.x + rv.x; v.y = lo.y + rv.y;
        v.z = hi.x + rv.z; v.w = hi.y + rv.w;
        *(float4*)&g_cr[rr] = v;
        ls += (double)v.x + (double)v.y + (double)v.z + (double)v.w;
        lq += (double)v.x * v.x + (double)v.y * v.y +
              (double)v.z * v.z + (double)v.w * v.w;
    }
    for (int off = 16; off > 0; off >>= 1) {
        ls += __shfl_down_sync(0xffffffffu, ls, off);
        lq += __shfl_down_sync(0xffffffffu, lq, off);
    }
    int wid = t >> 5;
    if ((t & 31) == 0) { reds[wid] = ls; redq[wid] = lq; }
    __syncthreads();
    if (wid == 0) {
        ls = (t < 4) ? reds[t] : 0.0;
        lq = (t < 4) ? redq[t] : 0.0;
        for (int off = 2; off > 0; off >>= 1) {
            ls += __shfl_down_sync(0xffffffffu, ls, off);
            lq += __shfl_down_sync(0xffffffffu, lq, off);
        }
        if (t == 0) {
            atomicAdd(&g_sumsA[ck][0], ls);
            atomicAdd(&g_sumsA[ck][1], lq);
        }
    }
}

// ---------------- final: norm inline, 1x1 conv over P + linear H->1 ---------
__global__ void k_out(const float* __restrict__ cw, const float* __restrict__ cb,
                      const float* __restrict__ lw, const float* __restrict__ lb,
                      float* __restrict__ out) {
    __shared__ float red[4][2];
    __shared__ float s_mu, s_r;
    int t = threadIdx.x;
    if (t == 0) {
        double mu  = g_sumsA[3][0] / (double)BNH_;
        double var = g_sumsA[3][1] / (double)BNH_ - mu * mu;
        s_mu = (float)mu;
        s_r  = (float)rsqrt(var + 1e-5);
    }
    __syncthreads();
    int h  = t & 63;
    int rl = t >> 6;
    int row = blockIdx.x * 4 + rl;
    int b = row / N_, n = row % N_;
    float v   = (g_cr[(long)row * 64 + h] - s_mu) * s_r;
    float lin = lw[h];
    int lane = t & 31;
    int w2   = (t >> 5) & 1;
    for (int p = 0; p < P_; ++p) {
        float x = cw[p] * v + cb[p];
        x = x > 0.f ? x : 0.f;
        float s = x * lin;
#pragma unroll
        for (int o = 16; o > 0; o >>= 1) s += __shfl_down_sync(0xffffffffu, s, o);
        if (lane == 0) red[rl][w2] = s;
        __syncthreads();
        if (h == 0) out[((long)b * P_ + p) * N_ + n] = red[rl][0] + red[rl][1] + lb[0];
        __syncthreads();
    }
}

// ---------------- launcher ---------------------------------------------------
extern "C" void kernel_launch(void* const* d_in, const int* in_sizes, int n_in,
                              void* d_out, int out_size) {
    const float* inputs    = (const float*)d_in[0];
    const float* adj_fwd   = (const float*)d_in[1];
    const float* pea_fwd   = (const float*)d_in[3];
    const float* w_in      = (const float*)d_in[5];
    const float* b_in      = (const float*)d_in[6];
    const float* res_w     = (const float*)d_in[7];
    const float* res_b     = (const float*)d_in[8];
    const float* gconv_w   = (const float*)d_in[9];
    const float* gconv_b   = (const float*)d_in[10];
    const float* gate1_w   = (const float*)d_in[11];
    const float* gate1_b   = (const float*)d_in[12];
    const float* gate2_w   = (const float*)d_in[13];
    const float* gate2_b   = (const float*)d_in[14];
    const float* reduce_w  = (const float*)d_in[15];
    const float* reduce_b  = (const float*)d_in[16];
    const float* gcn_adj_w = (const float*)d_in[17];
    const float* gcn_adj_b = (const float*)d_in[18];
    const float* gcn_pea_w = (const float*)d_in[19];
    const float* gcn_pea_b = (const float*)d_in[20];
    const float* out_cw    = (const float*)d_in[21];
    const float* out_cb    = (const float*)d_in[22];
    const float* out_lw    = (const float*)d_in[23];
    const float* out_lb    = (const float*)d_in[24];
    float* out = (float*)d_out;

    k_wsum<<<256, 256>>>(gcn_adj_w, gcn_pea_w);
    k_compact<<<2 * N_, 32>>>(adj_fwd, pea_fwd);

    const int lefts[4] = {0, 4, 7, 10};
    dim3 gl(N_, 2, 2);                 // (n, 32-batch group, mat)
    for (int ck = 0; ck < 4; ++ck) {
        k_A<<<BNH_ / 256, 256>>>(inputs, w_in, b_in, res_w, res_b,
                                 gconv_w, gconv_b, ck, lefts[ck]);
        k_layer0<<<gl, 128>>>(gcn_adj_b, gcn_pea_b);
        k_layer1<<<gl, 128>>>(gcn_adj_b, gcn_pea_b);
        k_gate<<<BNH_ / 64 / 32, 128>>>(gate1_w, gate1_b, gate2_w, gate2_b,
                                        reduce_w, reduce_b, ck);
    }
    k_out<<<(B_ * N_) / 4, 256>>>(out_cw, out_cb, out_lw, out_lb, out);
}

// round 16
// speedup vs baseline: 1.0132x; 1.0132x over previous
#include <cuda_runtime.h>

#define B_   64
#define T_   13
#define N_   325
#define H_   64
#define C_   4
#define S_   4
#define P_   12
#define NB_  1300
#define OFF_ 975
#define NH_  (N_*H_)        // 20800
#define BNH_ (B_*NH_)       // 1331200
#define ROW_ (B_*H_)        // 4096 floats per node row (node-major)

typedef unsigned long long u64;

// ---------------- scratch (device globals; no runtime alloc allowed) --------
__device__ float  g_gf  [BNH_];
__device__ float  g_res [BNH_];
__device__ float  g_h3T [BNH_];          // node-major [n][b*64+h]
__device__ float  g_cr  [BNH_];
__device__ float  g_H0T [2][C_][BNH_];   // node-major layer-0 outputs
__device__ float  g_C1  [2][C_][BNH_];   // batch-major (for k_gate)
__device__ float  g_Wsum[2][C_][2][H_*H_];
__device__ int    g_cols[2][N_][N_];
__device__ float  g_vals[2][N_][N_];
__device__ int    g_cnt [2][N_];
__device__ double g_sumsA[4][2];         // per-checkpoint (sum, sumsq)

// ---------------- f32x2 packed helpers (used by k_gate) ---------------------
__device__ __forceinline__ u64 pack2(float x, float y) {
    u64 r;
    asm("mov.b64 %0, {%1, %2};" : "=l"(r) : "f"(x), "f"(y));
    return r;
}
__device__ __forceinline__ float2 unpack2(u64 v) {
    float2 r;
    asm("mov.b64 {%0, %1}, %2;" : "=f"(r.x), "=f"(r.y) : "l"(v));
    return r;
}
__device__ __forceinline__ void fma2(u64& d, u64 a, u64 b) {
    asm("fma.rn.f32x2 %0, %1, %2, %0;" : "+l"(d) : "l"(a), "l"(b));
}
__device__ __forceinline__ void gemm_step(u64 accA[4], u64 accB[4],
                                          u64 a0, u64 a1, u64 a2, u64 a3,
                                          float4 w) {
    u64 wxy = pack2(w.x, w.y);
    u64 wzw = pack2(w.z, w.w);
    fma2(accA[0], a0, wxy); fma2(accB[0], a0, wzw);
    fma2(accA[1], a1, wxy); fma2(accB[1], a1, wzw);
    fma2(accA[2], a2, wxy); fma2(accB[2], a2, wzw);
    fma2(accA[3], a3, wxy); fma2(accB[3], a3, wzw);
}

// ---------------- scalar 4x4 helpers -----------------------------------------
__device__ __forceinline__ void fma16(float4 acc[4], float a0, float a1, float a2,
                                      float a3, float4 w) {
    acc[0].x = fmaf(a0, w.x, acc[0].x); acc[0].y = fmaf(a0, w.y, acc[0].y);
    acc[0].z = fmaf(a0, w.z, acc[0].z); acc[0].w = fmaf(a0, w.w, acc[0].w);
    acc[1].x = fmaf(a1, w.x, acc[1].x); acc[1].y = fmaf(a1, w.y, acc[1].y);
    acc[1].z = fmaf(a1, w.z, acc[1].z); acc[1].w = fmaf(a1, w.w, acc[1].w);
    acc[2].x = fmaf(a2, w.x, acc[2].x); acc[2].y = fmaf(a2, w.y, acc[2].y);
    acc[2].z = fmaf(a2, w.z, acc[2].z); acc[2].w = fmaf(a2, w.w, acc[2].w);
    acc[3].x = fmaf(a3, w.x, acc[3].x); acc[3].y = fmaf(a3, w.y, acc[3].y);
    acc[3].z = fmaf(a3, w.z, acc[3].z); acc[3].w = fmaf(a3, w.w, acc[3].w);
}
__device__ __forceinline__ float4 relu4(float4 v) {
    v.x = v.x > 0.f ? v.x : 0.f; v.y = v.y > 0.f ? v.y : 0.f;
    v.z = v.z > 0.f ? v.z : 0.f; v.w = v.w > 0.f ? v.w : 0.f;
    return v;
}
__device__ __forceinline__ void fma4v(float4& a, float w, float4 v) {
    a.x = fmaf(w, v.x, a.x); a.y = fmaf(w, v.y, a.y);
    a.z = fmaf(w, v.z, a.z); a.w = fmaf(w, v.w, a.w);
}

// ---------------- prep: Wsum[mat][c][l] = W[c,l,0] + W[c,l,1]; zero sums ----
__global__ void k_wsum(const float* __restrict__ aw, const float* __restrict__ pw) {
    int idx = blockIdx.x * blockDim.x + threadIdx.x;
    if (idx < 8) ((double*)g_sumsA)[idx] = 0.0;
    if (idx >= 2 * C_ * 2 * H_ * H_) return;
    int mat = idx >> 15;
    int r   = idx & 32767;
    int c   = r >> 13;
    int l   = (r >> 12) & 1;
    int e   = r & 4095;
    const float* src = mat ? pw : aw;
    int base = ((c * 2 + l) * 2) * 4096;
    ((float*)g_Wsum)[idx] = src[base + e] + src[base + 4096 + e];
}

// ---------------- prep: compact nonzeros of the last diagonal block ---------
__global__ void k_compact(const float* __restrict__ adjf, const float* __restrict__ peaf) {
    int rowid = blockIdx.x;
    int mat = rowid / N_;
    int n   = rowid % N_;
    const float* A = mat ? peaf : adjf;
    int lane = threadIdx.x;
    int cnt = 0;
    for (int base = 0; base < N_; base += 32) {
        int m = base + lane;
        float w = (m < N_) ? A[(long)(OFF_ + n) * NB_ + OFF_ + m] : 0.f;
        unsigned mask = __ballot_sync(0xffffffffu, w != 0.f);
        if (w != 0.f) {
            int pos = cnt + __popc(mask & ((1u << lane) - 1u));
            g_cols[mat][n][pos] = m;
            g_vals[mat][n][pos] = w;
        }
        cnt += __popc(mask);
    }
    if (lane == 0) g_cnt[mat][n] = cnt;
}

// ---------------- per-checkpoint: gf / residual / h3T (x + norm inline) -----
__global__ void k_A(const float* __restrict__ inp, const float* __restrict__ w_in,
                    const float* __restrict__ b_in, const float* __restrict__ res_w,
                    const float* __restrict__ res_b, const float* __restrict__ gcw,
                    const float* __restrict__ gcb, int ck, int left) {
    __shared__ float s_mu, s_r;
    if (threadIdx.x == 0) {
        if (ck > 0) {
            double mu  = g_sumsA[ck - 1][0] / (double)BNH_;
            double var = g_sumsA[ck - 1][1] / (double)BNH_ - mu * mu;
            s_mu = (float)mu;
            s_r  = (float)rsqrt(var + 1e-5);
        } else { s_mu = 0.f; s_r = 0.f; }
    }
    __syncthreads();
    int idx = blockIdx.x * blockDim.x + threadIdx.x;
    if (idx >= BNH_) return;
    int h = idx & 63;
    int n = (idx >> 6) % N_;
    int b = idx / NH_;
    float w0 = w_in[h], w1 = w_in[64 + h], bi = b_in[h];
    float gf = 0.f, rs = 0.f, v = 0.f;
#pragma unroll
    for (int s = 0; s < 4; ++s) {
        if (ck > 0 && s == 0) {
            v = (g_cr[idx] - s_mu) * s_r;
        } else {
            int t = (ck == 0) ? s : (left + s - 1);
            const float2 ip = *(const float2*)(inp + (((long)b * T_ + t) * N_ + n) * 2);
            v = ip.x * w0 + ip.y * w1 + bi;
        }
        gf += gcw[s] * v;
        rs += res_w[s] * v;
    }
    g_gf[idx]  = gf + gcb[0];
    g_res[idx] = rs + res_b[0];
    g_h3T[(long)n * ROW_ + b * 64 + h] = v;     // node-major
}

// -------- GCN layer 0: coalesced streaming SpMM + 4x4-tiled GEMMs -----------
// grid (N_, 2 batch-groups, 2 mats); block 128
__global__ void __launch_bounds__(128) k_layer0(const float* __restrict__ gbA,
                                                const float* __restrict__ gbP) {
    __shared__ int   scols[336];
    __shared__ float svals[336];
    __shared__ float sA[32][64];       // [b][h] slice for 32 batches
    int n   = blockIdx.x;
    int bg  = blockIdx.y;
    int mat = blockIdx.z;
    int t   = threadIdx.x;
    int cnt = g_cnt[mat][n];
    for (int i = t; i < cnt; i += 128) {
        scols[i] = g_cols[mat][n][i];
        svals[i] = g_vals[mat][n][i];
    }
    __syncthreads();

    {   // streaming SpMM: per nonzero, read contiguous 8KB slice of node row
        const float4* base = (const float4*)g_h3T + bg * 512 + t;
        float4 a0 = make_float4(0.f,0.f,0.f,0.f), a1 = a0, a2 = a0, a3 = a0;
        for (int i = 0; i < cnt; ++i) {
            const float4* src = base + (long)scols[i] * (ROW_ / 4);
            float w = svals[i];
            float4 v0 = src[0];
            float4 v1 = src[128];
            float4 v2 = src[256];
            float4 v3 = src[384];
            fma4v(a0, w, v0); fma4v(a1, w, v1);
            fma4v(a2, w, v2); fma4v(a3, w, v3);
        }
        float4* s4 = (float4*)sA;
        s4[t] = a0; s4[t + 128] = a1; s4[t + 256] = a2; s4[t + 384] = a3;
    }
    __syncthreads();

    int tx = t & 15, ty = t >> 4;      // ty 0..7 -> 4 batches each
    const float* gb = mat ? gbP : gbA;
#pragma unroll
    for (int c = 0; c < C_; ++c) {
        const float4* W4 = (const float4*)g_Wsum[mat][c][0] + tx;
        float4 bias = ((const float4*)(gb + (c * 2) * 64))[tx];
        float4 acc[4] = {bias, bias, bias, bias};
        const float* A0 = sA[ty * 4 + 0];
        const float* A1 = sA[ty * 4 + 1];
        const float* A2 = sA[ty * 4 + 2];
        const float* A3 = sA[ty * 4 + 3];
#pragma unroll 4
        for (int k = 0; k < 64; ++k)
            fma16(acc, A0[k], A1[k], A2[k], A3[k], __ldg(&W4[k * 16]));
        float* dst = g_H0T[mat][c] + (long)n * ROW_ + bg * 2048 + tx * 4;
#pragma unroll
        for (int j = 0; j < 4; ++j)
            *(float4*)(dst + (ty * 4 + j) * 64) = relu4(acc[j]);
    }
}

// -------- GCN layer 1: per-channel streaming SpMM + GEMM (C1 batch-major) ---
// grid (N_, 2, 2); block 128
__global__ void __launch_bounds__(128) k_layer1(const float* __restrict__ gbA,
                                                const float* __restrict__ gbP) {
    __shared__ int   scols[336];
    __shared__ float svals[336];
    __shared__ float sA[32][64];
    int n   = blockIdx.x;
    int bg  = blockIdx.y;
    int mat = blockIdx.z;
    int t   = threadIdx.x;
    int cnt = g_cnt[mat][n];
    for (int i = t; i < cnt; i += 128) {
        scols[i] = g_cols[mat][n][i];
        svals[i] = g_vals[mat][n][i];
    }
    __syncthreads();

    int tx = t & 15, ty = t >> 4;
    const float* gb = mat ? gbP : gbA;
#pragma unroll
    for (int c = 0; c < C_; ++c) {
        if (c) __syncthreads();        // prev GEMM finished reading sA
        {   // streaming SpMM from H0T[mat][c]
            const float4* base = (const float4*)g_H0T[mat][c] + bg * 512 + t;
            float4 a0 = make_float4(0.f,0.f,0.f,0.f), a1 = a0, a2 = a0, a3 = a0;
            for (int i = 0; i < cnt; ++i) {
                const float4* src = base + (long)scols[i] * (ROW_ / 4);
                float w = svals[i];
                float4 v0 = src[0];
                float4 v1 = src[128];
                float4 v2 = src[256];
                float4 v3 = src[384];
                fma4v(a0, w, v0); fma4v(a1, w, v1);
                fma4v(a2, w, v2); fma4v(a3, w, v3);
            }
            float4* s4 = (float4*)sA;
            s4[t] = a0; s4[t + 128] = a1; s4[t + 256] = a2; s4[t + 384] = a3;
        }
        __syncthreads();
        {   // GEMM with Wsum[mat][c][1] -> g_C1 batch-major
            const float4* W4 = (const float4*)g_Wsum[mat][c][1] + tx;
            float4 bias = ((const float4*)(gb + (c * 2 + 1) * 64))[tx];
            float4 acc[4] = {bias, bias, bias, bias};
            const float* A0 = sA[ty * 4 + 0];
            const float* A1 = sA[ty * 4 + 1];
            const float* A2 = sA[ty * 4 + 2];
            const float* A3 = sA[ty * 4 + 3];
#pragma unroll 4
            for (int k = 0; k < 64; ++k)
                fma16(acc, A0[k], A1[k], A2[k], A3[k], __ldg(&W4[k * 16]));
            float* dst = g_C1[mat][c] + n * 64 + tx * 4;
#pragma unroll
            for (int j = 0; j < 4; ++j)
                *(float4*)(dst + (long)(bg * 32 + ty * 4 + j) * NH_) = relu4(acc[j]);
        }
    }
}

// ------- gate -> combine -> reduce -> +residual, fused LN partial sums ------
__global__ void __launch_bounds__(128) k_gate(
        const float* __restrict__ g1w, const float* __restrict__ g1b,
        const float* __restrict__ g2w, const float* __restrict__ g2b,
        const float* __restrict__ rw,  const float* __restrict__ rb, int ck) {
    __shared__ float2 sBuf[32][64];
    __shared__ float2 sG1[32][64];
    __shared__ double reds[4], redq[4];
    int t = threadIdx.x;
    long row0 = (long)blockIdx.x * 32;

    {   // load gf tile (duplicated pairs)
        const float* src = g_gf + row0 * 64;
#pragma unroll
        for (int i = 0; i < 16; ++i) {
            int idx = t + 128 * i;
            float v = src[idx];
            ((float2*)sBuf)[idx] = make_float2(v, v);
        }
    }
    __syncthreads();

    int tx = t & 15, ty = t >> 4;
    {   // stage 1: relu(gf @ g1w + g1b) -> sG1 (duplicated)
        const float4* W4 = (const float4*)g1w + tx;
        float4 b1 = ((const float4*)g1b)[tx];
        u64 bA = pack2(b1.x, b1.y), bB = pack2(b1.z, b1.w);
        u64 accA[4] = {bA, bA, bA, bA};
        u64 accB[4] = {bB, bB, bB, bB};
        const float2* A0 = sBuf[ty * 4 + 0];
        const float2* A1 = sBuf[ty * 4 + 1];
        const float2* A2 = sBuf[ty * 4 + 2];
        const float2* A3 = sBuf[ty * 4 + 3];
#pragma unroll 4
        for (int k = 0; k < 64; ++k) {
            gemm_step(accA, accB,
                      *(const u64*)&A0[k], *(const u64*)&A1[k],
                      *(const u64*)&A2[k], *(const u64*)&A3[k],
                      __ldg(&W4[k * 16]));
        }
#pragma unroll
        for (int j = 0; j < 4; ++j) {
            float2 lo = unpack2(accA[j]);
            float2 hi = unpack2(accB[j]);
            float r0 = lo.x > 0.f ? lo.x : 0.f;
            float r1 = lo.y > 0.f ? lo.y : 0.f;
            float r2 = hi.x > 0.f ? hi.x : 0.f;
            float r3 = hi.y > 0.f ? hi.y : 0.f;
            sG1[ty * 4 + j][tx * 4 + 0] = make_float2(r0, r0);
            sG1[ty * 4 + j][tx * 4 + 1] = make_float2(r1, r1);
            sG1[ty * 4 + j][tx * 4 + 2] = make_float2(r2, r2);
            sG1[ty * 4 + j][tx * 4 + 3] = make_float2(r3, r3);
        }
    }
    __syncthreads();

    float4 rbv = ((const float4*)rb)[tx];
    u64 r3A = pack2(rbv.x, rbv.y), r3B = pack2(rbv.z, rbv.w);
    u64 acc3A[4] = {r3A, r3A, r3A, r3A};
    u64 acc3B[4] = {r3B, r3B, r3B, r3B};
#pragma unroll
    for (int q = 0; q < 4; ++q) {
        float4 b2 = ((const float4*)(g2b + q * 64))[tx];
        u64 bA = pack2(b2.x, b2.y), bB = pack2(b2.z, b2.w);
        u64 acc2A[4] = {bA, bA, bA, bA};
        u64 acc2B[4] = {bB, bB, bB, bB};
        {
            const float4* W4 = (const float4*)(g2w + q * 64) + tx;
            const float2* A0 = sG1[ty * 4 + 0];
            const float2* A1 = sG1[ty * 4 + 1];
            const float2* A2 = sG1[ty * 4 + 2];
            const float2* A3 = sG1[ty * 4 + 3];
#pragma unroll 4
            for (int k = 0; k < 64; ++k) {
                gemm_step(acc2A, acc2B,
                          *(const u64*)&A0[k], *(const u64*)&A1[k],
                          *(const u64*)&A2[k], *(const u64*)&A3[k],
                          __ldg(&W4[k * 64]));
            }
        }
        __syncthreads();
#pragma unroll
        for (int j = 0; j < 4; ++j) {
            long rr = (row0 + ty * 4 + j) * 64 + tx * 4;
            float4 ca = *(const float4*)&g_C1[0][q][rr];
            float4 cp = *(const float4*)&g_C1[1][q][rr];
            float2 lo = unpack2(acc2A[j]);
            float2 hi = unpack2(acc2B[j]);
            float g0 = 1.f / (1.f + expf(-lo.x));
            float g1 = 1.f / (1.f + expf(-lo.y));
            float g2 = 1.f / (1.f + expf(-hi.x));
            float g3 = 1.f / (1.f + expf(-hi.y));
            float o0 = g0 * ca.x + (1.f - g0) * cp.x;
            float o1 = g1 * ca.y + (1.f - g1) * cp.y;
            float o2 = g2 * ca.z + (1.f - g2) * cp.z;
            float o3 = g3 * ca.w + (1.f - g3) * cp.w;
            sBuf[ty * 4 + j][tx * 4 + 0] = make_float2(o0, o0);
            sBuf[ty * 4 + j][tx * 4 + 1] = make_float2(o1, o1);
            sBuf[ty * 4 + j][tx * 4 + 2] = make_float2(o2, o2);
            sBuf[ty * 4 + j][tx * 4 + 3] = make_float2(o3, o3);
        }
        __syncthreads();
        {
            const float4* W4 = (const float4*)(rw + (q * 64) * 64) + tx;
            const float2* A0 = sBuf[ty * 4 + 0];
            const float2* A1 = sBuf[ty * 4 + 1];
            const float2* A2 = sBuf[ty * 4 + 2];
            const float2* A3 = sBuf[ty * 4 + 3];
#pragma unroll 4
            for (int k = 0; k < 64; ++k) {
                gemm_step(acc3A, acc3B,
                          *(const u64*)&A0[k], *(const u64*)&A1[k],
                          *(const u64*)&A2[k], *(const u64*)&A3[k],
                          __ldg(&W4[k * 16]));
            }
        }
    }

    double ls = 0.0, lq = 0.0;
#pragma unroll
    for (int j = 0; j < 4; ++j) {
        long rr = (row0 + ty * 4 + j) * 64 + tx * 4;
        float4 rv = *(const float4*)&g_res[rr];
        float2 lo = unpack2(acc3A[j]);
        float2 hi = unpack2(acc3B[j]);
        float4 v;
        v.x = lo.x + rv.x; v.y = lo.y + rv.y;
        v.z = hi.x + rv.z; v.w = hi.y + rv.w;
        *(float4*)&g_cr[rr] = v;
        ls += (double)v.x + (double)v.y + (double)v.z + (double)v.w;
        lq += (double)v.x * v.x + (double)v.y * v.y +
              (double)v.z * v.z + (double)v.w * v.w;
    }
    for (int off = 16; off > 0; off >>= 1) {
        ls += __shfl_down_sync(0xffffffffu, ls, off);
        lq += __shfl_down_sync(0xffffffffu, lq, off);
    }
    int wid = t >> 5;
    if ((t & 31) == 0) { reds[wid] = ls; redq[wid] = lq; }
    __syncthreads();
    if (wid == 0) {
        ls = (t < 4) ? reds[t] : 0.0;
        lq = (t < 4) ? redq[t] : 0.0;
        for (int off = 2; off > 0; off >>= 1) {
            ls += __shfl_down_sync(0xffffffffu, ls, off);
            lq += __shfl_down_sync(0xffffffffu, lq, off);
        }
        if (t == 0) {
            atomicAdd(&g_sumsA[ck][0], ls);
            atomicAdd(&g_sumsA[ck][1], lq);
        }
    }
}

// ---------------- final: norm inline, 1x1 conv over P + linear H->1 ---------
__global__ void k_out(const float* __restrict__ cw, const float* __restrict__ cb,
                      const float* __restrict__ lw, const float* __restrict__ lb,
                      float* __restrict__ out) {
    __shared__ float red[4][2];
    __shared__ float s_mu, s_r;
    int t = threadIdx.x;
    if (t == 0) {
        double mu  = g_sumsA[3][0] / (double)BNH_;
        double var = g_sumsA[3][1] / (double)BNH_ - mu * mu;
        s_mu = (float)mu;
        s_r  = (float)rsqrt(var + 1e-5);
    }
    __syncthreads();
    int h  = t & 63;
    int rl = t >> 6;
    int row = blockIdx.x * 4 + rl;
    int b = row / N_, n = row % N_;
    float v   = (g_cr[(long)row * 64 + h] - s_mu) * s_r;
    float lin = lw[h];
    int lane = t & 31;
    int w2   = (t >> 5) & 1;
    for (int p = 0; p < P_; ++p) {
        float x = cw[p] * v + cb[p];
        x = x > 0.f ? x : 0.f;
        float s = x * lin;
#pragma unroll
        for (int o = 16; o > 0; o >>= 1) s += __shfl_down_sync(0xffffffffu, s, o);
        if (lane == 0) red[rl][w2] = s;
        __syncthreads();
        if (h == 0) out[((long)b * P_ + p) * N_ + n] = red[rl][0] + red[rl][1] + lb[0];
        __syncthreads();
    }
}

// ---------------- launcher ---------------------------------------------------
extern "C" void kernel_launch(void* const* d_in, const int* in_sizes, int n_in,
                              void* d_out, int out_size) {
    const float* inputs    = (const float*)d_in[0];
    const float* adj_fwd   = (const float*)d_in[1];
    const float* pea_fwd   = (const float*)d_in[3];
    const float* w_in      = (const float*)d_in[5];
    const float* b_in      = (const float*)d_in[6];
    const float* res_w     = (const float*)d_in[7];
    const float* res_b     = (const float*)d_in[8];
    const float* gconv_w   = (const float*)d_in[9];
    const float* gconv_b   = (const float*)d_in[10];
    const float* gate1_w   = (const float*)d_in[11];
    const float* gate1_b   = (const float*)d_in[12];
    const float* gate2_w   = (const float*)d_in[13];
    const float* gate2_b   = (const float*)d_in[14];
    const float* reduce_w  = (const float*)d_in[15];
    const float* reduce_b  = (const float*)d_in[16];
    const float* gcn_adj_w = (const float*)d_in[17];
    const float* gcn_adj_b = (const float*)d_in[18];
    const float* gcn_pea_w = (const float*)d_in[19];
    const float* gcn_pea_b = (const float*)d_in[20];
    const float* out_cw    = (const float*)d_in[21];
    const float* out_cb    = (const float*)d_in[22];
    const float* out_lw    = (const float*)d_in[23];
    const float* out_lb    = (const float*)d_in[24];
    float* out = (float*)d_out;

    k_wsum<<<256, 256>>>(gcn_adj_w, gcn_pea_w);
    k_compact<<<2 * N_, 32>>>(adj_fwd, pea_fwd);

    const int lefts[4] = {0, 4, 7, 10};
    dim3 gl(N_, 2, 2);                 // (n, 32-batch group, mat)
    for (int ck = 0; ck < 4; ++ck) {
        k_A<<<BNH_ / 256, 256>>>(inputs, w_in, b_in, res_w, res_b,
                                 gconv_w, gconv_b, ck, lefts[ck]);
        k_layer0<<<gl, 128>>>(gcn_adj_b, gcn_pea_b);
        k_layer1<<<gl, 128>>>(gcn_adj_b, gcn_pea_b);
        k_gate<<<BNH_ / 64 / 32, 128>>>(gate1_w, gate1_b, gate2_w, gate2_b,
                                        reduce_w, reduce_b, ck);
    }
    k_out<<<(B_ * N_) / 4, 256>>>(out_cw, out_cb, out_lw, out_lb, out);
}

// round 17
// speedup vs baseline: 1.0149x; 1.0017x over previous
#include <cuda_runtime.h>

#define B_   64
#define T_   13
#define N_   325
#define H_   64
#define C_   4
#define S_   4
#define P_   12
#define NB_  1300
#define OFF_ 975
#define NH_  (N_*H_)        // 20800
#define BNH_ (B_*NH_)       // 1331200
#define ROW_ (B_*H_)        // 4096 floats per node row (node-major)

typedef unsigned long long u64;

// ---------------- scratch (device globals; no runtime alloc allowed) --------
__device__ float  g_gf  [BNH_];
__device__ float  g_res [BNH_];
__device__ float  g_h3T [BNH_];          // node-major [n][b*64+h]
__device__ float  g_cr  [BNH_];
__device__ float  g_H0T [2][C_][BNH_];   // node-major layer-0 outputs
__device__ float  g_C1  [2][C_][BNH_];   // batch-major (for k_gate)
__device__ float  g_Wsum[2][C_][2][H_*H_];
__device__ int    g_cols[2][N_][N_];
__device__ float  g_vals[2][N_][N_];
__device__ int    g_cnt [2][N_];
__device__ double g_sumsA[4][2];         // per-checkpoint (sum, sumsq)

// ---------------- f32x2 packed helpers (used by k_gate) ---------------------
__device__ __forceinline__ u64 pack2(float x, float y) {
    u64 r;
    asm("mov.b64 %0, {%1, %2};" : "=l"(r) : "f"(x), "f"(y));
    return r;
}
__device__ __forceinline__ float2 unpack2(u64 v) {
    float2 r;
    asm("mov.b64 {%0, %1}, %2;" : "=f"(r.x), "=f"(r.y) : "l"(v));
    return r;
}
__device__ __forceinline__ void fma2(u64& d, u64 a, u64 b) {
    asm("fma.rn.f32x2 %0, %1, %2, %0;" : "+l"(d) : "l"(a), "l"(b));
}
__device__ __forceinline__ void gemm_step(u64 accA[4], u64 accB[4],
                                          u64 a0, u64 a1, u64 a2, u64 a3,
                                          float4 w) {
    u64 wxy = pack2(w.x, w.y);
    u64 wzw = pack2(w.z, w.w);
    fma2(accA[0], a0, wxy); fma2(accB[0], a0, wzw);
    fma2(accA[1], a1, wxy); fma2(accB[1], a1, wzw);
    fma2(accA[2], a2, wxy); fma2(accB[2], a2, wzw);
    fma2(accA[3], a3, wxy); fma2(accB[3], a3, wzw);
}

// ---------------- scalar 4x4 helpers -----------------------------------------
__device__ __forceinline__ void fma16(float4 acc[4], float a0, float a1, float a2,
                                      float a3, float4 w) {
    acc[0].x = fmaf(a0, w.x, acc[0].x); acc[0].y = fmaf(a0, w.y, acc[0].y);
    acc[0].z = fmaf(a0, w.z, acc[0].z); acc[0].w = fmaf(a0, w.w, acc[0].w);
    acc[1].x = fmaf(a1, w.x, acc[1].x); acc[1].y = fmaf(a1, w.y, acc[1].y);
    acc[1].z = fmaf(a1, w.z, acc[1].z); acc[1].w = fmaf(a1, w.w, acc[1].w);
    acc[2].x = fmaf(a2, w.x, acc[2].x); acc[2].y = fmaf(a2, w.y, acc[2].y);
    acc[2].z = fmaf(a2, w.z, acc[2].z); acc[2].w = fmaf(a2, w.w, acc[2].w);
    acc[3].x = fmaf(a3, w.x, acc[3].x); acc[3].y = fmaf(a3, w.y, acc[3].y);
    acc[3].z = fmaf(a3, w.z, acc[3].z); acc[3].w = fmaf(a3, w.w, acc[3].w);
}
__device__ __forceinline__ float4 relu4(float4 v) {
    v.x = v.x > 0.f ? v.x : 0.f; v.y = v.y > 0.f ? v.y : 0.f;
    v.z = v.z > 0.f ? v.z : 0.f; v.w = v.w > 0.f ? v.w : 0.f;
    return v;
}
__device__ __forceinline__ void fma4v(float4& a, float w, float4 v) {
    a.x = fmaf(w, v.x, a.x); a.y = fmaf(w, v.y, a.y);
    a.z = fmaf(w, v.z, a.z); a.w = fmaf(w, v.w, a.w);
}

// ---------------- prep: Wsum[mat][c][l] = W[c,l,0] + W[c,l,1]; zero sums ----
__global__ void k_wsum(const float* __restrict__ aw, const float* __restrict__ pw) {
    int idx = blockIdx.x * blockDim.x + threadIdx.x;
    if (idx < 8) ((double*)g_sumsA)[idx] = 0.0;
    if (idx >= 2 * C_ * 2 * H_ * H_) return;
    int mat = idx >> 15;
    int r   = idx & 32767;
    int c   = r >> 13;
    int l   = (r >> 12) & 1;
    int e   = r & 4095;
    const float* src = mat ? pw : aw;
    int base = ((c * 2 + l) * 2) * 4096;
    ((float*)g_Wsum)[idx] = src[base + e] + src[base + 4096 + e];
}

// ---------------- prep: compact nonzeros of the last diagonal block ---------
__global__ void k_compact(const float* __restrict__ adjf, const float* __restrict__ peaf) {
    int rowid = blockIdx.x;
    int mat = rowid / N_;
    int n   = rowid % N_;
    const float* A = mat ? peaf : adjf;
    int lane = threadIdx.x;
    int cnt = 0;
    for (int base = 0; base < N_; base += 32) {
        int m = base + lane;
        float w = (m < N_) ? A[(long)(OFF_ + n) * NB_ + OFF_ + m] : 0.f;
        unsigned mask = __ballot_sync(0xffffffffu, w != 0.f);
        if (w != 0.f) {
            int pos = cnt + __popc(mask & ((1u << lane) - 1u));
            g_cols[mat][n][pos] = m;
            g_vals[mat][n][pos] = w;
        }
        cnt += __popc(mask);
    }
    if (lane == 0) g_cnt[mat][n] = cnt;
}

// ---------------- per-checkpoint: gf / residual / h3T (x + norm inline) -----
__global__ void k_A(const float* __restrict__ inp, const float* __restrict__ w_in,
                    const float* __restrict__ b_in, const float* __restrict__ res_w,
                    const float* __restrict__ res_b, const float* __restrict__ gcw,
                    const float* __restrict__ gcb, int ck, int left) {
    __shared__ float s_mu, s_r;
    if (threadIdx.x == 0) {
        if (ck > 0) {
            double mu  = g_sumsA[ck - 1][0] / (double)BNH_;
            double var = g_sumsA[ck - 1][1] / (double)BNH_ - mu * mu;
            s_mu = (float)mu;
            s_r  = (float)rsqrt(var + 1e-5);
        } else { s_mu = 0.f; s_r = 0.f; }
    }
    __syncthreads();
    int idx = blockIdx.x * blockDim.x + threadIdx.x;
    if (idx >= BNH_) return;
    int h = idx & 63;
    int n = (idx >> 6) % N_;
    int b = idx / NH_;
    float w0 = w_in[h], w1 = w_in[64 + h], bi = b_in[h];
    float gf = 0.f, rs = 0.f, v = 0.f;
#pragma unroll
    for (int s = 0; s < 4; ++s) {
        if (ck > 0 && s == 0) {
            v = (g_cr[idx] - s_mu) * s_r;
        } else {
            int t = (ck == 0) ? s : (left + s - 1);
            const float2 ip = *(const float2*)(inp + (((long)b * T_ + t) * N_ + n) * 2);
            v = ip.x * w0 + ip.y * w1 + bi;
        }
        gf += gcw[s] * v;
        rs += res_w[s] * v;
    }
    g_gf[idx]  = gf + gcb[0];
    g_res[idx] = rs + res_b[0];
    g_h3T[(long)n * ROW_ + b * 64 + h] = v;     // node-major
}

// -------- GCN layer 0: coalesced streaming SpMM + 4x4-tiled GEMMs -----------
// grid (N_, 2 batch-groups, 2 mats); block 128
__global__ void __launch_bounds__(128) k_layer0(const float* __restrict__ gbA,
                                                const float* __restrict__ gbP) {
    __shared__ int   scols[336];
    __shared__ float svals[336];
    __shared__ float sA[32][64];       // [b][h] slice for 32 batches
    int n   = blockIdx.x;
    int bg  = blockIdx.y;
    int mat = blockIdx.z;
    int t   = threadIdx.x;
    int cnt = g_cnt[mat][n];
    for (int i = t; i < cnt; i += 128) {
        scols[i] = g_cols[mat][n][i];
        svals[i] = g_vals[mat][n][i];
    }
    __syncthreads();

    {   // streaming SpMM: per nonzero, read contiguous 8KB slice of node row
        const float4* base = (const float4*)g_h3T + bg * 512 + t;
        float4 a0 = make_float4(0.f,0.f,0.f,0.f), a1 = a0, a2 = a0, a3 = a0;
        for (int i = 0; i < cnt; ++i) {
            const float4* src = base + (long)scols[i] * (ROW_ / 4);
            float w = svals[i];
            float4 v0 = src[0];
            float4 v1 = src[128];
            float4 v2 = src[256];
            float4 v3 = src[384];
            fma4v(a0, w, v0); fma4v(a1, w, v1);
            fma4v(a2, w, v2); fma4v(a3, w, v3);
        }
        float4* s4 = (float4*)sA;
        s4[t] = a0; s4[t + 128] = a1; s4[t + 256] = a2; s4[t + 384] = a3;
    }
    __syncthreads();

    int tx = t & 15, ty = t >> 4;      // ty 0..7 -> 4 batches each
    const float* gb = mat ? gbP : gbA;
#pragma unroll
    for (int c = 0; c < C_; ++c) {
        const float4* W4 = (const float4*)g_Wsum[mat][c][0] + tx;
        float4 bias = ((const float4*)(gb + (c * 2) * 64))[tx];
        float4 acc[4] = {bias, bias, bias, bias};
        const float* A0 = sA[ty * 4 + 0];
        const float* A1 = sA[ty * 4 + 1];
        const float* A2 = sA[ty * 4 + 2];
        const float* A3 = sA[ty * 4 + 3];
#pragma unroll 4
        for (int k = 0; k < 64; ++k)
            fma16(acc, A0[k], A1[k], A2[k], A3[k], __ldg(&W4[k * 16]));
        float* dst = g_H0T[mat][c] + (long)n * ROW_ + bg * 2048 + tx * 4;
#pragma unroll
        for (int j = 0; j < 4; ++j)
            *(float4*)(dst + (ty * 4 + j) * 64) = relu4(acc[j]);
    }
}

// -------- GCN layer 1: per-channel streaming SpMM + GEMM (C1 batch-major) ---
// grid (N_, 2, 2); block 128
__global__ void __launch_bounds__(128) k_layer1(const float* __restrict__ gbA,
                                                const float* __restrict__ gbP) {
    __shared__ int   scols[336];
    __shared__ float svals[336];
    __shared__ float sA[32][64];
    int n   = blockIdx.x;
    int bg  = blockIdx.y;
    int mat = blockIdx.z;
    int t   = threadIdx.x;
    int cnt = g_cnt[mat][n];
    for (int i = t; i < cnt; i += 128) {
        scols[i] = g_cols[mat][n][i];
        svals[i] = g_vals[mat][n][i];
    }
    __syncthreads();

    int tx = t & 15, ty = t >> 4;
    const float* gb = mat ? gbP : gbA;
#pragma unroll
    for (int c = 0; c < C_; ++c) {
        if (c) __syncthreads();        // prev GEMM finished reading sA
        {   // streaming SpMM from H0T[mat][c]
            const float4* base = (const float4*)g_H0T[mat][c] + bg * 512 + t;
            float4 a0 = make_float4(0.f,0.f,0.f,0.f), a1 = a0, a2 = a0, a3 = a0;
            for (int i = 0; i < cnt; ++i) {
                const float4* src = base + (long)scols[i] * (ROW_ / 4);
                float w = svals[i];
                float4 v0 = src[0];
                float4 v1 = src[128];
                float4 v2 = src[256];
                float4 v3 = src[384];
                fma4v(a0, w, v0); fma4v(a1, w, v1);
                fma4v(a2, w, v2); fma4v(a3, w, v3);
            }
            float4* s4 = (float4*)sA;
            s4[t] = a0; s4[t + 128] = a1; s4[t + 256] = a2; s4[t + 384] = a3;
        }
        __syncthreads();
        {   // GEMM with Wsum[mat][c][1] -> g_C1 batch-major
            const float4* W4 = (const float4*)g_Wsum[mat][c][1] + tx;
            float4 bias = ((const float4*)(gb + (c * 2 + 1) * 64))[tx];
            float4 acc[4] = {bias, bias, bias, bias};
            const float* A0 = sA[ty * 4 + 0];
            const float* A1 = sA[ty * 4 + 1];
            const float* A2 = sA[ty * 4 + 2];
            const float* A3 = sA[ty * 4 + 3];
#pragma unroll 4
            for (int k = 0; k < 64; ++k)
                fma16(acc, A0[k], A1[k], A2[k], A3[k], __ldg(&W4[k * 16]));
            float* dst = g_C1[mat][c] + n * 64 + tx * 4;
#pragma unroll
            for (int j = 0; j < 4; ++j)
                *(float4*)(dst + (long)(bg * 32 + ty * 4 + j) * NH_) = relu4(acc[j]);
        }
    }
}

// ------- gate -> combine -> reduce -> +residual, fused LN partial sums ------
__global__ void __launch_bounds__(128) k_gate(
        const float* __restrict__ g1w, const float* __restrict__ g1b,
        const float* __restrict__ g2w, const float* __restrict__ g2b,
        const float* __restrict__ rw,  const float* __restrict__ rb, int ck) {
    __shared__ float2 sBuf[32][64];
    __shared__ float2 sG1[32][64];
    __shared__ double reds[4], redq[4];
    int t = threadIdx.x;
    long row0 = (long)blockIdx.x * 32;

    {   // load gf tile (duplicated pairs)
        const float* src = g_gf + row0 * 64;
#pragma unroll
        for (int i = 0; i < 16; ++i) {
            int idx = t + 128 * i;
            float v = src[idx];
            ((float2*)sBuf)[idx] = make_float2(v, v);
        }
    }
    __syncthreads();

    int tx = t & 15, ty = t >> 4;
    {   // stage 1: relu(gf @ g1w + g1b) -> sG1 (duplicated)
        const float4* W4 = (const float4*)g1w + tx;
        float4 b1 = ((const float4*)g1b)[tx];
        u64 bA = pack2(b1.x, b1.y), bB = pack2(b1.z, b1.w);
        u64 accA[4] = {bA, bA, bA, bA};
        u64 accB[4] = {bB, bB, bB, bB};
        const float2* A0 = sBuf[ty * 4 + 0];
        const float2* A1 = sBuf[ty * 4 + 1];
        const float2* A2 = sBuf[ty * 4 + 2];
        const float2* A3 = sBuf[ty * 4 + 3];
#pragma unroll 4
        for (int k = 0; k < 64; ++k) {
            gemm_step(accA, accB,
                      *(const u64*)&A0[k], *(const u64*)&A1[k],
                      *(const u64*)&A2[k], *(const u64*)&A3[k],
                      __ldg(&W4[k * 16]));
        }
#pragma unroll
        for (int j = 0; j < 4; ++j) {
            float2 lo = unpack2(accA[j]);
            float2 hi = unpack2(accB[j]);
            float r0 = lo.x > 0.f ? lo.x : 0.f;
            float r1 = lo.y > 0.f ? lo.y : 0.f;
            float r2 = hi.x > 0.f ? hi.x : 0.f;
            float r3 = hi.y > 0.f ? hi.y : 0.f;
            sG1[ty * 4 + j][tx * 4 + 0] = make_float2(r0, r0);
            sG1[ty * 4 + j][tx * 4 + 1] = make_float2(r1, r1);
            sG1[ty * 4 + j][tx * 4 + 2] = make_float2(r2, r2);
            sG1[ty * 4 + j][tx * 4 + 3] = make_float2(r3, r3);
        }
    }
    __syncthreads();

    float4 rbv = ((const float4*)rb)[tx];
    u64 r3A = pack2(rbv.x, rbv.y), r3B = pack2(rbv.z, rbv.w);
    u64 acc3A[4] = {r3A, r3A, r3A, r3A};
    u64 acc3B[4] = {r3B, r3B, r3B, r3B};
#pragma unroll
    for (int q = 0; q < 4; ++q) {
        float4 b2 = ((const float4*)(g2b + q * 64))[tx];
        u64 bA = pack2(b2.x, b2.y), bB = pack2(b2.z, b2.w);
        u64 acc2A[4] = {bA, bA, bA, bA};
        u64 acc2B[4] = {bB, bB, bB, bB};
        {
            const float4* W4 = (const float4*)(g2w + q * 64) + tx;
            const float2* A0 = sG1[ty * 4 + 0];
            const float2* A1 = sG1[ty * 4 + 1];
            const float2* A2 = sG1[ty * 4 + 2];
            const float2* A3 = sG1[ty * 4 + 3];
#pragma unroll 4
            for (int k = 0; k < 64; ++k) {
                gemm_step(acc2A, acc2B,
                          *(const u64*)&A0[k], *(const u64*)&A1[k],
                          *(const u64*)&A2[k], *(const u64*)&A3[k],
                          __ldg(&W4[k * 64]));
            }
        }
        __syncthreads();
#pragma unroll
        for (int j = 0; j < 4; ++j) {
            long rr = (row0 + ty * 4 + j) * 64 + tx * 4;
            float4 ca = *(const float4*)&g_C1[0][q][rr];
            float4 cp = *(const float4*)&g_C1[1][q][rr];
            float2 lo = unpack2(acc2A[j]);
            float2 hi = unpack2(acc2B[j]);
            float g0 = 1.f / (1.f + expf(-lo.x));
            float g1 = 1.f / (1.f + expf(-lo.y));
            float g2 = 1.f / (1.f + expf(-hi.x));
            float g3 = 1.f / (1.f + expf(-hi.y));
            float o0 = g0 * ca.x + (1.f - g0) * cp.x;
            float o1 = g1 * ca.y + (1.f - g1) * cp.y;
            float o2 = g2 * ca.z + (1.f - g2) * cp.z;
            float o3 = g3 * ca.w + (1.f - g3) * cp.w;
            sBuf[ty * 4 + j][tx * 4 + 0] = make_float2(o0, o0);
            sBuf[ty * 4 + j][tx * 4 + 1] = make_float2(o1, o1);
            sBuf[ty * 4 + j][tx * 4 + 2] = make_float2(o2, o2);
            sBuf[ty * 4 + j][tx * 4 + 3] = make_float2(o3, o3);
        }
        __syncthreads();
        {
            const float4* W4 = (const float4*)(rw + (q * 64) * 64) + tx;
            const float2* A0 = sBuf[ty * 4 + 0];
            const float2* A1 = sBuf[ty * 4 + 1];
            const float2* A2 = sBuf[ty * 4 + 2];
            const float2* A3 = sBuf[ty * 4 + 3];
#pragma unroll 4
            for (int k = 0; k < 64; ++k) {
                gemm_step(acc3A, acc3B,
                          *(const u64*)&A0[k], *(const u64*)&A1[k],
                          *(const u64*)&A2[k], *(const u64*)&A3[k],
                          __ldg(&W4[k * 16]));
            }
        }
    }

    double ls = 0.0, lq = 0.0;
#pragma unroll
    for (int j = 0; j < 4; ++j) {
        long rr = (row0 + ty * 4 + j) * 64 + tx * 4;
        float4 rv = *(const float4*)&g_res[rr];
        float2 lo = unpack2(acc3A[j]);
        float2 hi = unpack2(acc3B[j]);
        float4 v;
        v.x = lo.x + rv.x; v.y = lo.y + rv.y;
        v.z = hi.x + rv.z; v.w = hi.y + rv.w;
        *(float4*)&g_cr[rr] = v;
        ls += (double)v.x + (double)v.y + (double)v.z + (double)v.w;
        lq += (double)v.x * v.x + (double)v.y * v.y +
              (double)v.z * v.z + (double)v.w * v.w;
    }
    for (int off = 16; off > 0; off >>= 1) {
        ls += __shfl_down_sync(0xffffffffu, ls, off);
        lq += __shfl_down_sync(0xffffffffu, lq, off);
    }
    int wid = t >> 5;
    if ((t & 31) == 0) { reds[wid] = ls; redq[wid] = lq; }
    __syncthreads();
    if (wid == 0) {
        ls = (t < 4) ? reds[t] : 0.0;
        lq = (t < 4) ? redq[t] : 0.0;
        for (int off = 2; off > 0; off >>= 1) {
            ls += __shfl_down_sync(0xffffffffu, ls, off);
            lq += __shfl_down_sync(0xffffffffu, lq, off);
        }
        if (t == 0) {
            atomicAdd(&g_sumsA[ck][0], ls);
            atomicAdd(&g_sumsA[ck][1], lq);
        }
    }
}

// ---------------- final: norm inline, 1x1 conv over P + linear H->1 ---------
__global__ void k_out(const float* __restrict__ cw, const float* __restrict__ cb,
                      const float* __restrict__ lw, const float* __restrict__ lb,
                      float* __restrict__ out) {
    __shared__ float red[4][2];
    __shared__ float s_mu, s_r;
    int t = threadIdx.x;
    if (t == 0) {
        double mu  = g_sumsA[3][0] / (double)BNH_;
        double var = g_sumsA[3][1] / (double)BNH_ - mu * mu;
        s_mu = (float)mu;
        s_r  = (float)rsqrt(var + 1e-5);
    }
    __syncthreads();
    int h  = t & 63;
    int rl = t >> 6;
    int row = blockIdx.x * 4 + rl;
    int b = row / N_, n = row % N_;
    float v   = (g_cr[(long)row * 64 + h] - s_mu) * s_r;
    float lin = lw[h];
    int lane = t & 31;
    int w2   = (t >> 5) & 1;
    for (int p = 0; p < P_; ++p) {
        float x = cw[p] * v + cb[p];
        x = x > 0.f ? x : 0.f;
        float s = x * lin;
#pragma unroll
        for (int o = 16; o > 0; o >>= 1) s += __shfl_down_sync(0xffffffffu, s, o);
        if (lane == 0) red[rl][w2] = s;
        __syncthreads();
        if (h == 0) out[((long)b * P_ + p) * N_ + n] = red[rl][0] + red[rl][1] + lb[0];
        __syncthreads();
    }
}

// ---------------- launcher ---------------------------------------------------
extern "C" void kernel_launch(void* const* d_in, const int* in_sizes, int n_in,
                              void* d_out, int out_size) {
    const float* inputs    = (const float*)d_in[0];
    const float* adj_fwd   = (const float*)d_in[1];
    const float* pea_fwd   = (const float*)d_in[3];
    const float* w_in      = (const float*)d_in[5];
    const float* b_in      = (const float*)d_in[6];
    const float* res_w     = (const float*)d_in[7];
    const float* res_b     = (const float*)d_in[8];
    const float* gconv_w   = (const float*)d_in[9];
    const float* gconv_b   = (const float*)d_in[10];
    const float* gate1_w   = (const float*)d_in[11];
    const float* gate1_b   = (const float*)d_in[12];
    const float* gate2_w   = (const float*)d_in[13];
    const float* gate2_b   = (const float*)d_in[14];
    const float* reduce_w  = (const float*)d_in[15];
    const float* reduce_b  = (const float*)d_in[16];
    const float* gcn_adj_w = (const float*)d_in[17];
    const float* gcn_adj_b = (const float*)d_in[18];
    const float* gcn_pea_w = (const float*)d_in[19];
    const float* gcn_pea_b = (const float*)d_in[20];
    const float* out_cw    = (const float*)d_in[21];
    const float* out_cb    = (const float*)d_in[22];
    const float* out_lw    = (const float*)d_in[23];
    const float* out_lb    = (const float*)d_in[24];
    float* out = (float*)d_out;

    k_wsum<<<256, 256>>>(gcn_adj_w, gcn_pea_w);
    k_compact<<<2 * N_, 32>>>(adj_fwd, pea_fwd);

    const int lefts[4] = {0, 4, 7, 10};
    dim3 gl(N_, 2, 2);                 // (n, 32-batch group, mat)
    for (int ck = 0; ck < 4; ++ck) {
        k_A<<<BNH_ / 256, 256>>>(inputs, w_in, b_in, res_w, res_b,
                                 gconv_w, gconv_b, ck, lefts[ck]);
        k_layer0<<<gl, 128>>>(gcn_adj_b, gcn_pea_b);
        k_layer1<<<gl, 128>>>(gcn_adj_b, gcn_pea_b);
        k_gate<<<BNH_ / 64 / 32, 128>>>(gate1_w, gate1_b, gate2_w, gate2_b,
                                        reduce_w, reduce_b, ck);
    }
    k_out<<<(B_ * N_) / 4, 256>>>(out_cw, out_cb, out_lw, out_lb, out);
}